// round 1
// baseline (speedup 1.0000x reference)
#include <cuda_runtime.h>
#include <math.h>

#define B_  512
#define T_  512
#define H_  100
#define DI_ 101
#define DO_ 2

// 104.8 MB scratch for the input projection (allowed: __device__ global, no runtime alloc)
__device__ float g_xp[(size_t)B_ * T_ * H_];

// ---------------------------------------------------------------------------
// Kernel A: xp[r][j] = sum_i input[r][i] * W_x[j][i] + b[j]   (r = b*T+t)
// 2048 persistent-ish blocks, 128 threads, 16-row tiles, 4x4 register microtile
// ---------------------------------------------------------------------------
__global__ void __launch_bounds__(128) xp_gemm_kernel(
    const float* __restrict__ inp,   // [B*T, DI]
    const float* __restrict__ Wx,    // [H, DI]
    const float* __restrict__ bias)  // [H]
{
    __shared__ __align__(16) float Wx_s[DI_ * H_];   // transposed: [i][j], stride 100
    __shared__ __align__(16) float in_s[DI_ * 16];   // transposed: [i][r], stride 16

    const int tid = threadIdx.x;
    const int tx  = tid & 31;   // column quad index (active tx < 25 -> j = 4*tx)
    const int ty  = tid >> 5;   // row quad index (4 warps -> rows 4*ty .. 4*ty+3)

    // Load W_x transposed into shared (once per block)
    for (int idx = tid; idx < DI_ * H_; idx += 128) {
        int j = idx / DI_;
        int i = idx - j * DI_;
        Wx_s[i * H_ + j] = Wx[idx];
    }

    float bj[4] = {0.f, 0.f, 0.f, 0.f};
    if (tx < 25) {
#pragma unroll
        for (int c = 0; c < 4; c++) bj[c] = bias[4 * tx + c];
    }

    const int ntiles = (B_ * T_) / 16;
    for (int tile = blockIdx.x; tile < ntiles; tile += gridDim.x) {
        __syncthreads();  // previous iteration's readers of in_s are done
        const int rbase = tile * 16;
        for (int idx = tid; idx < 16 * DI_; idx += 128) {
            int r = idx / DI_;
            int i = idx - r * DI_;
            in_s[i * 16 + r] = inp[(size_t)(rbase + r) * DI_ + i];
        }
        __syncthreads();

        if (tx < 25) {
            float acc[4][4];
#pragma unroll
            for (int rr = 0; rr < 4; rr++)
#pragma unroll
                for (int cc = 0; cc < 4; cc++) acc[rr][cc] = bj[cc];

#pragma unroll 4
            for (int i = 0; i < DI_; i++) {
                float4 av = *(const float4*)(in_s + i * 16 + 4 * ty);
                float4 wv = *(const float4*)(Wx_s + i * H_ + 4 * tx);
                acc[0][0] = fmaf(av.x, wv.x, acc[0][0]);
                acc[0][1] = fmaf(av.x, wv.y, acc[0][1]);
                acc[0][2] = fmaf(av.x, wv.z, acc[0][2]);
                acc[0][3] = fmaf(av.x, wv.w, acc[0][3]);
                acc[1][0] = fmaf(av.y, wv.x, acc[1][0]);
                acc[1][1] = fmaf(av.y, wv.y, acc[1][1]);
                acc[1][2] = fmaf(av.y, wv.z, acc[1][2]);
                acc[1][3] = fmaf(av.y, wv.w, acc[1][3]);
                acc[2][0] = fmaf(av.z, wv.x, acc[2][0]);
                acc[2][1] = fmaf(av.z, wv.y, acc[2][1]);
                acc[2][2] = fmaf(av.z, wv.z, acc[2][2]);
                acc[2][3] = fmaf(av.z, wv.w, acc[2][3]);
                acc[3][0] = fmaf(av.w, wv.x, acc[3][0]);
                acc[3][1] = fmaf(av.w, wv.y, acc[3][1]);
                acc[3][2] = fmaf(av.w, wv.z, acc[3][2]);
                acc[3][3] = fmaf(av.w, wv.w, acc[3][3]);
            }
#pragma unroll
            for (int rr = 0; rr < 4; rr++) {
                int row = rbase + 4 * ty + rr;
                float4 o;
                o.x = acc[rr][0]; o.y = acc[rr][1]; o.z = acc[rr][2]; o.w = acc[rr][3];
                *(float4*)(g_xp + (size_t)row * H_ + 4 * tx) = o;
            }
        }
    }
}

// ---------------------------------------------------------------------------
// Kernel B: the sequential scan.
// 128 CTAs x 256 threads. CTA owns 4 chains. Thread (g = tid>>7, j = tid&127)
// owns ah for chains (4*blk + 2g, 4*blk + 2g + 1) at hidden unit j (j < 100).
// W_h transposed in shared [k][j] (stride 104), h double-buffered [k][b].
// One __syncthreads per step.
// ---------------------------------------------------------------------------
__global__ void __launch_bounds__(256) scan_kernel(
    const float* __restrict__ noise,   // [B, T, H]
    const float* __restrict__ Wh,      // [H, H]  (W_h_ah[j][k])
    const float* __restrict__ ah0,     // [H]
    float* __restrict__ hstore)        // [B, T, H]
{
    __shared__ __align__(16) float Wt[H_ * 104];      // [k][j]
    __shared__ __align__(16) float hbuf[2][H_ * 4];   // [k][b_local]

    const int tid = threadIdx.x;
    const int g   = tid >> 7;        // 0 or 1
    const int j   = tid & 127;       // hidden unit (active if < 100)
    const int b0  = blockIdx.x * 4 + 2 * g;
    const int b1  = b0 + 1;

    // Load W_h transposed: Wt[k*104 + j] = Wh[j*H_ + k]
    for (int idx = tid; idx < H_ * H_; idx += 256) {
        int jj = idx / H_;
        int k  = idx - jj * H_;
        Wt[k * 104 + jj] = Wh[idx];
    }

    float ahx = 0.f, ahy = 0.f;
    if (j < H_) {
        float a0 = ah0[j];
        ahx = a0; ahy = a0;
        float h0 = tanhf(fmaxf(a0, 0.f));
        hbuf[0][j * 4 + 2 * g]     = h0;
        hbuf[0][j * 4 + 2 * g + 1] = h0;
    }
    __syncthreads();

    const size_t rb0 = (size_t)b0 * T_;
    const size_t rb1 = (size_t)b1 * T_;

    int buf = 0;
    for (int t = 0; t < T_; t++) {
        // Issue streaming loads early (hide DRAM latency behind the matvec)
        float xpv0 = 0.f, xpv1 = 0.f, nz0 = 0.f, nz1 = 0.f;
        if (j < H_) {
            xpv0 = g_xp[(rb0 + t) * H_ + j];
            xpv1 = g_xp[(rb1 + t) * H_ + j];
            nz0  = noise[(rb0 + t) * H_ + j];
            nz1  = noise[(rb1 + t) * H_ + j];
        }

        const float* hb = hbuf[buf];
        if (j < H_) {
            float acc0 = 0.f, acc1 = 0.f;
#pragma unroll 4
            for (int k = 0; k < H_; k++) {
                float2 hp = *(const float2*)(hb + k * 4 + 2 * g);  // broadcast
                float  w  = Wt[k * 104 + j];
                acc0 = fmaf(hp.x, w, acc0);
                acc1 = fmaf(hp.y, w, acc1);
            }
            // ah = ah + 0.1*(-ah + mv + xp)
            ahx = fmaf(0.1f, (acc0 + xpv0) - ahx, ahx);
            ahy = fmaf(0.1f, (acc1 + xpv1) - ahy, ahy);
            float h0 = tanhf(fmaxf(ahx, 0.f)) + nz0;
            float h1 = tanhf(fmaxf(ahy, 0.f)) + nz1;
            hbuf[buf ^ 1][j * 4 + 2 * g]     = h0;
            hbuf[buf ^ 1][j * 4 + 2 * g + 1] = h1;
            hstore[(rb0 + t) * H_ + j] = h0;
            hstore[(rb1 + t) * H_ + j] = h1;
        }
        buf ^= 1;
        __syncthreads();
    }
}

// ---------------------------------------------------------------------------
// Kernel C: output[r][d] = sum_j hstore[r][j] * W_y[d][j]   (d = 0,1)
// One warp per row; coalesced loads; warp shuffle reduction.
// ---------------------------------------------------------------------------
__global__ void __launch_bounds__(256) outproj_kernel(
    const float* __restrict__ hst,   // [B*T, H]
    const float* __restrict__ Wy,    // [DO, H]
    float* __restrict__ out)         // [B*T, DO]
{
    __shared__ float wy_s[DO_ * H_];
    const int tid = threadIdx.x;
    for (int idx = tid; idx < DO_ * H_; idx += 256) wy_s[idx] = Wy[idx];
    __syncthreads();

    const int lane = tid & 31;
    const int w    = tid >> 5;
    const size_t row = (size_t)blockIdx.x * 8 + w;

    float a0 = 0.f, a1 = 0.f;
    for (int j = lane; j < H_; j += 32) {
        float h = hst[row * H_ + j];
        a0 = fmaf(h, wy_s[j],       a0);
        a1 = fmaf(h, wy_s[H_ + j],  a1);
    }
#pragma unroll
    for (int off = 16; off > 0; off >>= 1) {
        a0 += __shfl_down_sync(0xffffffffu, a0, off);
        a1 += __shfl_down_sync(0xffffffffu, a1, off);
    }
    if (lane == 0) {
        out[row * DO_ + 0] = a0;
        out[row * DO_ + 1] = a1;
    }
}

// ---------------------------------------------------------------------------
extern "C" void kernel_launch(void* const* d_in, const int* in_sizes, int n_in,
                              void* d_out, int out_size)
{
    const float* inp   = (const float*)d_in[0];  // [B,T,DI]
    const float* noise = (const float*)d_in[1];  // [B,T,H]
    const float* Wx    = (const float*)d_in[2];  // [H,DI]
    const float* bias  = (const float*)d_in[3];  // [H]
    const float* Wh    = (const float*)d_in[4];  // [H,H]
    const float* Wy    = (const float*)d_in[5];  // [DO,H]
    const float* ah0   = (const float*)d_in[6];  // [H]

    float* out    = (float*)d_out;                      // [B,T,DO] first
    float* hstore = out + (size_t)B_ * T_ * DO_;        // [B,T,H] second

    xp_gemm_kernel<<<2048, 128>>>(inp, Wx, bias);
    scan_kernel<<<B_ / 4, 256>>>(noise, Wh, ah0, hstore);
    outproj_kernel<<<(B_ * T_) / 8, 256>>>(hstore, Wy, out);
}